// round 16
// baseline (speedup 1.0000x reference)
#include <cuda_runtime.h>

typedef unsigned long long u64;

#define BATCH   4
#define CHAN    16
#define MAXT    2048
#define FDIM    32
#define TOKENS  256
#define KW      2049
#define HALFK   1024
#define NBF     (BATCH * FDIM)

#define TOK_PER_CHUNK 32
#define NCHUNK        8
#define CGRP    4
#define CPC     (CHAN / CGRP)           // 4 channels per CTA
#define TT      512                     // tap-tile size (multiple of 256)

// per-(b,row) normalized wavelets
__device__ float2 g_wav[NBF * KW];

// ---------------------------------------------------------------------------
// Kernel 1: per-row normalized wavelets (shuffle reduction, 2 barriers)
// ---------------------------------------------------------------------------
__global__ void wavelet_kernel(const float* __restrict__ fs,
                               const float* __restrict__ freqs,
                               const float* __restrict__ ncyc)
{
    __shared__ float red[32];
    __shared__ float s_norm;
    int bf = blockIdx.x;
    int b = bf >> 5, f = bf & 31;
    int tid = threadIdx.x;
    int lane = tid & 31, wid = tid >> 5;

    float fv  = fmaxf(freqs[f], 0.1f);
    float ncv = fmaxf(ncyc[f], 1.0f);
    float fsv = fs[b];
    float w0 = 6.2831855f * fv;          // fp32(2*pi)*f, ref op order
    float sigma = ncv / w0;
    float denom = 2.0f * sigma * sigma;

    float wr[3], wi[3];
    float s = 0.0f;
    #pragma unroll
    for (int it = 0; it < 3; ++it) {
        int k = tid + it * 1024;
        wr[it] = 0.0f; wi[it] = 0.0f;
        if (k < KW) {
            float ts = (float)(k - HALFK) / fsv;
            float env = expf(-(ts * ts) / denom);
            float sn, cs;
            sincosf(w0 * ts, &sn, &cs);
            wr[it] = cs * env;
            wi[it] = sn * env;
            s += sqrtf(wr[it] * wr[it] + wi[it] * wi[it]);
        }
    }
    #pragma unroll
    for (int o = 16; o > 0; o >>= 1)
        s += __shfl_xor_sync(0xffffffffu, s, o);
    if (lane == 0) red[wid] = s;
    __syncthreads();
    if (wid == 0) {
        float v = red[lane];
        #pragma unroll
        for (int o = 16; o > 0; o >>= 1)
            v += __shfl_xor_sync(0xffffffffu, v, o);
        if (lane == 0) s_norm = v + 1e-8f;
    }
    __syncthreads();
    float norm = s_norm;                 // norm over FULL support (ref-exact)

    #pragma unroll
    for (int it = 0; it < 3; ++it) {
        int k = tid + it * 1024;
        if (k < KW)
            g_wav[bf * KW + k] = make_float2(wr[it] / norm, wi[it] / norm);
    }
}

// ---------------------------------------------------------------------------
// replication of the reference's fp32 vertical-grid arithmetic
// ---------------------------------------------------------------------------
__device__ __forceinline__ void row_blend(int f, int& r0, int& r1,
                                          float& wy0, float& wy1)
{
    float yd  = __fdiv_rn(2.0f, 31.0f);
    float ys  = __fmul_rn((float)f, yd);
    float yv  = __fadd_rn(-1.0f, ys);
    float gy  = __fmul_rn(__fmul_rn(__fadd_rn(yv, 1.0f), 0.5f), 31.0f);
    float y0f = floorf(gy);
    r0 = (int)y0f;
    wy1 = __fadd_rn(gy, -y0f);
    wy0 = __fadd_rn(1.0f, -wy1);
    r1 = r0 + 1;
    if (r1 > 31) { wy1 = 0.0f; r1 = 31; }
}

// ---------------------------------------------------------------------------
// packed f32x2 helpers
// ---------------------------------------------------------------------------
__device__ __forceinline__ u64 dup2(float x) {
    unsigned int u = __float_as_uint(x);
    u64 r;
    asm("mov.b64 %0, {%1, %1};" : "=l"(r) : "r"(u));
    return r;
}
__device__ __forceinline__ u64 fma2(u64 a, u64 b, u64 c) {
    u64 d;
    asm("fma.rn.f32x2 %0, %1, %2, %3;" : "=l"(d) : "l"(a), "l"(b), "l"(c));
    return d;
}
__device__ __forceinline__ u64 add2(u64 a, u64 b) {
    u64 d;
    asm("add.rn.f32x2 %0, %1, %2;" : "=l"(d) : "l"(a), "l"(b));
    return d;
}
__device__ __forceinline__ float2 unpack2(u64 v) {
    unsigned int lo, hi;
    asm("mov.b64 {%0, %1}, %2;" : "=r"(lo), "=r"(hi) : "l"(v));
    return make_float2(__uint_as_float(lo), __uint_as_float(hi));
}

// TwoSum compensated accumulate: (S, C) += p (exact subtract via fma*-1)
__device__ __forceinline__ void twosum(u64& S, u64& C, u64 p, u64 neg1) {
    u64 t  = add2(S, p);
    u64 z  = fma2(S, neg1, t);
    u64 tz = fma2(z, neg1, t);
    u64 e1 = fma2(tz, neg1, S);
    u64 e2 = fma2(z, neg1, p);
    C = add2(C, add2(e1, e2));
    S = t;
}

// bit-exact replication of the reference's fp32 horizontal grid arithmetic
__device__ __forceinline__ float token_gx_exact(int j, float t) {
    float delta = __fdiv_rn(1.0f, 255.0f);
    float step  = __fmul_rn((float)j, delta);
    float xc    = __fadd_rn(-1.0f, __fmul_rn(step, t));
    return __fmul_rn(__fmul_rn(__fadd_rn(xc, 1.0f), 0.5f), 2047.0f);
}

// smem layout: w tile + x tile + per-thread S/C accumulator bank
#define WBSLOT     (TT + 8)                 // 520 u64 slots, 16B aligned
#define WBBYTES    (WBSLOT * 8)             // 4160
#define XSTRIDE    777                      // span(<=250) + TT + pad, odd
#define XSBYTES    (CPC * XSTRIDE * 4)      // 12432
#define ACCSLOT    272                      // per-accum stride (u64), skewed
#define ACCBYTES   (8 * ACCSLOT * 8)        // 17408
#define SMEM_BYTES (WBBYTES + XSBYTES + ACCBYTES)   // 34000 -> 5 CTAs/SM

// ---------------------------------------------------------------------------
// Kernel 2: 256 threads = 4 chan x 16 token-lanes x 4 tap-quarters,
// 2 tokens/thread. Tap-tiled (TT=512), 5-sigma window, padding-skip.
// S/C accumulators live in skewed smem (flush every 64 taps) ->
// 51-reg cap -> 5 CTAs/SM.
// ---------------------------------------------------------------------------
__global__ void __launch_bounds__(256, 5)
cwt_kernel(const float* __restrict__ x, const float* __restrict__ fs,
           const int* __restrict__ seq_lens, const float* __restrict__ freqs,
           const float* __restrict__ ncyc, float* __restrict__ out)
{
    extern __shared__ char smem[];
    float2* wb2 = (float2*)smem;
    u64*    wbu = (u64*)smem;
    float*  xs  = (float*)(smem + WBBYTES);
    u64*    acc = (u64*)(smem + WBBYTES + XSBYTES);

    int bf = blockIdx.x;
    int b = bf >> 5, f = bf & 31;
    int chunk = blockIdx.y;
    int cg    = blockIdx.z;
    int tid = threadIdx.x;

    // per-thread skewed accumulator slot (conflict-free 8B access)
    int sb = tid + (tid >> 4);
    // zero own S/C slots (no sync needed: private slots)
    #pragma unroll
    for (int a = 0; a < 8; ++a) acc[a * ACCSLOT + sb] = 0ull;

    int L = seq_lens[b];
    float Lf = (float)L;

    // ref-exact end_x / t
    float aa   = __fadd_rn(Lf, -1.0f);
    float bb   = __fmul_rn(2.0f, aa);
    float cc   = __fdiv_rn(bb, 2047.0f);
    float endx = __fadd_rn(-1.0f, cc);
    float tT   = __fadd_rn(endx, 1.0f);

    // vertical rows + weights (support governed by lower row r0)
    int r0, r1; float wy0, wy1;
    row_blend(f, r0, r1, wy0, wy1);

    float fsv = fs[b];
    float fv0  = fmaxf(freqs[r0], 0.1f);
    float ncv0 = fmaxf(ncyc[r0], 1.0f);
    float sig_samp = ncv0 * fsv / (6.2831855f * fv0);
    int hw = min(HALFK, (int)ceilf(5.0f * sig_samp));   // 5-sigma window
    if (hw < 1) hw = 1;
    int n  = 2 * hw + 2;
    int nn = (n + 255) & ~255;             // multiple of 256 (T4 mult of 64)

    int j0 = chunk * TOK_PER_CHUNK;
    int t0min = (int)floorf(token_gx_exact(j0, tT));
    int t0max = (int)floorf(token_gx_exact(j0 + TOK_PER_CHUNK - 1, tT));
    int span  = t0max - t0min;
    int base  = t0min - hw;

    // CTA-wide active tap range (all-zero-padding taps skipped); 256-aligned
    int u_lo = max(0, (hw - t0max)) & ~255;                 // round down
    int u_hi = min(nn, (MAXT - base + 255) & ~255);         // round up

    // thread mapping: channel (low), token-lane, tap-quarter (high)
    int c  = tid & 3;
    int tl = (tid >> 2) & 15;
    int q  = tid >> 6;
    int jA = j0 + tl, jB = j0 + tl + 16;

    float gxA = token_gx_exact(jA, tT);
    float gxB = token_gx_exact(jB, tT);
    float x0A = floorf(gxA), x0B = floorf(gxB);
    int t0A = (int)x0A, t0B = (int)x0B;
    float wx1A = __fadd_rn(gxA, -x0A);
    float wx1B = __fadd_rn(gxB, -x0B);
    float wx0A = __fadd_rn(1.0f, -wx1A);
    float wx0B = __fadd_rn(1.0f, -wx1B);
    if (t0A + 1 > MAXT - 1) wx1A = 0.0f;   // ref's valid mask on x1 gather
    if (t0B + 1 > MAXT - 1) wx1B = 0.0f;

    // fixed across tiles: staging for tile tb is already shifted by tb
    const float* xA = xs + c * XSTRIDE + (t0A - t0min);
    const float* xB = xs + c * XSTRIDE + (t0B - t0min);
    const float* xgb = x + (size_t)(b * CHAN + cg * CPC + c) * MAXT;

    const float2* wavA = g_wav + (b * FDIM + r0) * KW;
    const float2* wavB = g_wav + (b * FDIM + r1) * KW;

    u64 neg1 = dup2(-1.0f);
    int lx = tid >> 2;                     // x-stage lane within channel (0..63)

    for (int tb = u_lo; tb < u_hi; tb += TT) {
        int Tlen = min(TT, u_hi - tb);     // multiple of 256
        int T4 = Tlen >> 2;                // per-quarter taps, multiple of 64

        __syncthreads();                   // prev tile fully consumed

        // stage wavelet tile: wb[k] = padded-blend slot (tb+k), k in [0, Tlen+4)
        for (int k = tid; k < Tlen + 4; k += 256) {
            int u  = tb + k;
            int kg = HALFK - hw + u - 2;
            float2 v = make_float2(0.0f, 0.0f);
            if (u >= 2 && u <= n && kg <= KW - 1) {
                float2 a2 = wavA[kg], b2 = wavB[kg];
                v = make_float2(fmaf(wy1, b2.x, wy0 * a2.x),
                                fmaf(wy1, b2.y, wy0 * a2.y));
            }
            wb2[k] = v;
        }
        // stage x tile: xs[c][i] = x[base + tb + i], i in [0, span+Tlen+2)
        {
            int lenx = span + Tlen + 2;
            float* xr = xs + c * XSTRIDE;
            for (int i = lx; i < lenx; i += 64) {
                int g = base + tb + i;
                xr[i] = (g >= 0 && g < MAXT) ? xgb[g] : 0.0f;
            }
        }
        __syncthreads();

        // accumulate this quarter: local tap l = q*T4 + k, k in [0, T4)
        int lq = q * T4;                   // even (T4 mult of 64)
        const u64*  wq  = wbu + lq;
        const float* xAq = xA + lq;
        const float* xBq = xB + lq;
        u64 wp = wq[1];                    // slot u = tb+lq+1

        for (int kb = 0; kb < T4; kb += 64) {
            u64 aA0=0, aA1=0, aB0=0, aB1=0;
            #pragma unroll 8
            for (int k2 = 0; k2 < 64; k2 += 2) {
                int k = kb + k2;
                ulonglong2 W = *(const ulonglong2*)(wq + k + 2);  // 16B aligned
                u64 xa0 = dup2(xAq[k]);
                u64 xb0 = dup2(xBq[k]);
                aA0 = fma2(W.x, xa0, aA0);
                aA1 = fma2(wp,  xa0, aA1);
                aB0 = fma2(W.x, xb0, aB0);
                aB1 = fma2(wp,  xb0, aB1);
                u64 xa1 = dup2(xAq[k + 1]);
                u64 xb1 = dup2(xBq[k + 1]);
                aA0 = fma2(W.y, xa1, aA0);
                aA1 = fma2(W.x, xa1, aA1);
                aB0 = fma2(W.y, xb1, aB0);
                aB1 = fma2(W.x, xb1, aB1);
                wp = W.y;
            }
            // flush into smem-resident S/C (compensated)
            {
                u64 S, C;
                S = acc[0 * ACCSLOT + sb]; C = acc[4 * ACCSLOT + sb];
                twosum(S, C, aA0, neg1);
                acc[0 * ACCSLOT + sb] = S; acc[4 * ACCSLOT + sb] = C;
                S = acc[1 * ACCSLOT + sb]; C = acc[5 * ACCSLOT + sb];
                twosum(S, C, aA1, neg1);
                acc[1 * ACCSLOT + sb] = S; acc[5 * ACCSLOT + sb] = C;
                S = acc[2 * ACCSLOT + sb]; C = acc[6 * ACCSLOT + sb];
                twosum(S, C, aB0, neg1);
                acc[2 * ACCSLOT + sb] = S; acc[6 * ACCSLOT + sb] = C;
                S = acc[3 * ACCSLOT + sb]; C = acc[7 * ACCSLOT + sb];
                twosum(S, C, aB1, neg1);
                acc[3 * ACCSLOT + sb] = S; acc[7 * ACCSLOT + sb] = C;
            }
        }
    }

    // fold own S+C, then cross-quarter gather (q==0 threads)
    __syncthreads();
    u64 P[4];
    #pragma unroll
    for (int a = 0; a < 4; ++a)
        P[a] = add2(acc[a * ACCSLOT + sb], acc[(a + 4) * ACCSLOT + sb]);

    if (q) return;

    int pidx = tid & 63;
    #pragma unroll
    for (int qq = 1; qq < 4; ++qq) {
        int t2 = qq * 64 + pidx;
        int sb2 = t2 + (t2 >> 4);
        #pragma unroll
        for (int a = 0; a < 4; ++a)
            P[a] = add2(P[a], add2(acc[a * ACCSLOT + sb2],
                                   acc[(a + 4) * ACCSLOT + sb2]));
    }

    float2 ZA0 = unpack2(P[0]), ZA1 = unpack2(P[1]);
    float2 ZB0 = unpack2(P[2]), ZB1 = unpack2(P[3]);

    // horizontal combine (vertical blend already folded into the wavelet)
    float rA = __fadd_rn(__fmul_rn(ZA0.x, wx0A), __fmul_rn(ZA1.x, wx1A));
    float iA = __fadd_rn(__fmul_rn(ZA0.y, wx0A), __fmul_rn(ZA1.y, wx1A));
    float rB = __fadd_rn(__fmul_rn(ZB0.x, wx0B), __fmul_rn(ZB1.x, wx1B));
    float iB = __fadd_rn(__fmul_rn(ZB0.y, wx0B), __fmul_rn(ZB1.y, wx1B));

    float magA = __fsqrt_rn(__fadd_rn(__fadd_rn(__fmul_rn(rA, rA),
                                                __fmul_rn(iA, iA)), 1e-8f));
    float magB = __fsqrt_rn(__fadd_rn(__fadd_rn(__fmul_rn(rB, rB),
                                                __fmul_rn(iB, iB)), 1e-8f));
    float phA = __fdiv_rn(atan2f(iA, rA), 3.14159274f);
    float phB = __fdiv_rn(atan2f(iB, rB), 3.14159274f);

    int cglob = cg * CPC + c;
    size_t obase = ((size_t)(b * CHAN + cglob) * 2) * FDIM + f;
    out[(obase) * TOKENS + jA]        = magA;
    out[(obase + FDIM) * TOKENS + jA] = phA;
    out[(obase) * TOKENS + jB]        = magB;
    out[(obase + FDIM) * TOKENS + jB] = phB;
}

// ---------------------------------------------------------------------------
extern "C" void kernel_launch(void* const* d_in, const int* in_sizes, int n_in,
                              void* d_out, int out_size)
{
    const float* x    = (const float*)d_in[0];
    const float* fs   = (const float*)d_in[1];
    const int*   sl   = (const int*)d_in[2];
    const float* fr   = (const float*)d_in[3];
    const float* nc   = (const float*)d_in[4];
    float* out = (float*)d_out;

    cudaFuncSetAttribute(cwt_kernel, cudaFuncAttributeMaxDynamicSharedMemorySize,
                         SMEM_BYTES);

    wavelet_kernel<<<NBF, 1024>>>(fs, fr, nc);
    dim3 grid(NBF, NCHUNK, CGRP);
    cwt_kernel<<<grid, 256, SMEM_BYTES>>>(x, fs, sl, fr, nc, out);
}

// round 17
// speedup vs baseline: 1.2878x; 1.2878x over previous
#include <cuda_runtime.h>

typedef unsigned long long u64;

#define BATCH   4
#define CHAN    16
#define MAXT    2048
#define FDIM    32
#define TOKENS  256
#define KW      2049
#define HALFK   1024
#define NBF     (BATCH * FDIM)

#define TOK_PER_CHUNK 32
#define NCHUNK        8
#define CGRP    4
#define CPC     (CHAN / CGRP)           // 4 channels per CTA
#define TT      512                     // tap-tile size (multiple of 128)

// per-(b,row) normalized wavelets
__device__ float2 g_wav[NBF * KW];

// ---------------------------------------------------------------------------
// Kernel 1: per-row normalized wavelets.
// Norm is analytic: |w(k)| = env(k) exactly, and
//   sum_{|k|<=1024} exp(-k^2/(2*sig^2)) = sig*sqrt(2*pi)*erf(1024.5/(sig*sqrt2))
// (Poisson-summation error <= e^-38 for sig >= 1.74). Purely multiplicative
// vs the reference's fp32 sum (~1e-6) -> phase bit-unaffected, mag ~1e-6.
// No reduction, no barriers.
// ---------------------------------------------------------------------------
__global__ void wavelet_kernel(const float* __restrict__ fs,
                               const float* __restrict__ freqs,
                               const float* __restrict__ ncyc)
{
    int bf = blockIdx.x;
    int b = bf >> 5, f = bf & 31;
    int tid = threadIdx.x;

    float fv  = fmaxf(freqs[f], 0.1f);
    float ncv = fmaxf(ncyc[f], 1.0f);
    float fsv = fs[b];
    float w0 = 6.2831855f * fv;          // fp32(2*pi)*f, ref op order
    float sigma = ncv / w0;
    float denom = 2.0f * sigma * sigma;

    // analytic norm of sum(env) over the full +-1024 support
    float sig_samp = ncv * fsv / w0;     // sigma in samples
    float norm = sig_samp * 2.5066283f *
                 erff(1024.5f / (sig_samp * 1.4142135f)) + 1e-8f;
    float inv = 1.0f / norm;

    #pragma unroll
    for (int it = 0; it < 3; ++it) {
        int k = tid + it * 1024;
        if (k < KW) {
            float ts = (float)(k - HALFK) / fsv;
            float env = expf(-(ts * ts) / denom);
            float sn, cs;
            sincosf(w0 * ts, &sn, &cs);
            g_wav[bf * KW + k] = make_float2(cs * env * inv, sn * env * inv);
        }
    }
}

// ---------------------------------------------------------------------------
// replication of the reference's fp32 vertical-grid arithmetic
// ---------------------------------------------------------------------------
__device__ __forceinline__ void row_blend(int f, int& r0, int& r1,
                                          float& wy0, float& wy1)
{
    float yd  = __fdiv_rn(2.0f, 31.0f);
    float ys  = __fmul_rn((float)f, yd);
    float yv  = __fadd_rn(-1.0f, ys);
    float gy  = __fmul_rn(__fmul_rn(__fadd_rn(yv, 1.0f), 0.5f), 31.0f);
    float y0f = floorf(gy);
    r0 = (int)y0f;
    wy1 = __fadd_rn(gy, -y0f);
    wy0 = __fadd_rn(1.0f, -wy1);
    r1 = r0 + 1;
    if (r1 > 31) { wy1 = 0.0f; r1 = 31; }
}

// ---------------------------------------------------------------------------
// packed f32x2 helpers
// ---------------------------------------------------------------------------
__device__ __forceinline__ u64 dup2(float x) {
    unsigned int u = __float_as_uint(x);
    u64 r;
    asm("mov.b64 %0, {%1, %1};" : "=l"(r) : "r"(u));
    return r;
}
__device__ __forceinline__ u64 fma2(u64 a, u64 b, u64 c) {
    u64 d;
    asm("fma.rn.f32x2 %0, %1, %2, %3;" : "=l"(d) : "l"(a), "l"(b), "l"(c));
    return d;
}
__device__ __forceinline__ u64 add2(u64 a, u64 b) {
    u64 d;
    asm("add.rn.f32x2 %0, %1, %2;" : "=l"(d) : "l"(a), "l"(b));
    return d;
}
__device__ __forceinline__ float2 unpack2(u64 v) {
    unsigned int lo, hi;
    asm("mov.b64 {%0, %1}, %2;" : "=r"(lo), "=r"(hi) : "l"(v));
    return make_float2(__uint_as_float(lo), __uint_as_float(hi));
}

// TwoSum compensated accumulate: (S, C) += p (exact subtract via fma*-1)
__device__ __forceinline__ void twosum(u64& S, u64& C, u64 p, u64 neg1) {
    u64 t  = add2(S, p);
    u64 z  = fma2(S, neg1, t);
    u64 tz = fma2(z, neg1, t);
    u64 e1 = fma2(tz, neg1, S);
    u64 e2 = fma2(z, neg1, p);
    C = add2(C, add2(e1, e2));
    S = t;
}

// bit-exact replication of the reference's fp32 horizontal grid arithmetic
__device__ __forceinline__ float token_gx_exact(int j, float t) {
    float delta = __fdiv_rn(1.0f, 255.0f);
    float step  = __fmul_rn((float)j, delta);
    float xc    = __fadd_rn(-1.0f, __fmul_rn(step, t));
    return __fmul_rn(__fmul_rn(__fadd_rn(xc, 1.0f), 0.5f), 2047.0f);
}

// smem layout: w tile + x tile (per tap-tile pass)
#define WBSLOT     (TT + 8)                 // 520 u64 slots, 16B aligned
#define WBBYTES    (WBSLOT * 8)             // 4160
#define XSTRIDE    777                      // span(<=250) + TT + pad, odd
#define SMEM_BYTES (WBBYTES + CPC * XSTRIDE * 4)   // 16592

// ---------------------------------------------------------------------------
// Kernel 2: 256 threads = 4 chan x 16 token-lanes x 4 tap-quarters,
// 2 tokens/thread (tl, tl+16). Tap-tiled (TT=512), 5-sigma window,
// padding-skip clamp [u_lo, u_hi). Compensated packed-complex accumulation;
// cross-quarter smem reduction. (Bit-identical to the round-15 cwt kernel.)
// ---------------------------------------------------------------------------
__global__ void __launch_bounds__(256, 4)
cwt_kernel(const float* __restrict__ x, const float* __restrict__ fs,
           const int* __restrict__ seq_lens, const float* __restrict__ freqs,
           const float* __restrict__ ncyc, float* __restrict__ out)
{
    extern __shared__ char smem[];
    float2* wb2 = (float2*)smem;
    u64*    wbu = (u64*)smem;
    float*  xs  = (float*)(smem + WBBYTES);

    int bf = blockIdx.x;
    int b = bf >> 5, f = bf & 31;
    int chunk = blockIdx.y;
    int cg    = blockIdx.z;
    int tid = threadIdx.x;

    int L = seq_lens[b];
    float Lf = (float)L;

    // ref-exact end_x / t
    float aa   = __fadd_rn(Lf, -1.0f);
    float bb   = __fmul_rn(2.0f, aa);
    float cc   = __fdiv_rn(bb, 2047.0f);
    float endx = __fadd_rn(-1.0f, cc);
    float tT   = __fadd_rn(endx, 1.0f);

    // vertical rows + weights (support governed by lower row r0)
    int r0, r1; float wy0, wy1;
    row_blend(f, r0, r1, wy0, wy1);

    float fsv = fs[b];
    float fv0  = fmaxf(freqs[r0], 0.1f);
    float ncv0 = fmaxf(ncyc[r0], 1.0f);
    float sig_samp = ncv0 * fsv / (6.2831855f * fv0);
    int hw = min(HALFK, (int)ceilf(5.0f * sig_samp));   // 5-sigma window
    if (hw < 1) hw = 1;
    int n  = 2 * hw + 2;
    int nn = (n + 127) & ~127;             // multiple of 128 (4 x 32-blocks)

    int j0 = chunk * TOK_PER_CHUNK;
    int t0min = (int)floorf(token_gx_exact(j0, tT));
    int t0max = (int)floorf(token_gx_exact(j0 + TOK_PER_CHUNK - 1, tT));
    int span  = t0max - t0min;
    int base  = t0min - hw;

    // CTA-wide active tap range: sample index = base + (t0 - t0min) + u.
    int u_lo = max(0, (hw - t0max)) & ~127;                 // round down
    int u_hi = min(nn, (MAXT - base + 127) & ~127);         // round up

    // thread mapping: channel (low), token-lane, tap-quarter (high)
    int c  = tid & 3;
    int tl = (tid >> 2) & 15;
    int q  = tid >> 6;
    int jA = j0 + tl, jB = j0 + tl + 16;

    float gxA = token_gx_exact(jA, tT);
    float gxB = token_gx_exact(jB, tT);
    float x0A = floorf(gxA), x0B = floorf(gxB);
    int t0A = (int)x0A, t0B = (int)x0B;
    float wx1A = __fadd_rn(gxA, -x0A);
    float wx1B = __fadd_rn(gxB, -x0B);
    float wx0A = __fadd_rn(1.0f, -wx1A);
    float wx0B = __fadd_rn(1.0f, -wx1B);
    if (t0A + 1 > MAXT - 1) wx1A = 0.0f;   // ref's valid mask on x1 gather
    if (t0B + 1 > MAXT - 1) wx1B = 0.0f;

    // fixed across tiles: staging for tile tb is already shifted by tb
    const float* xA = xs + c * XSTRIDE + (t0A - t0min);
    const float* xB = xs + c * XSTRIDE + (t0B - t0min);
    const float* xgb = x + (size_t)(b * CHAN + cg * CPC + c) * MAXT;

    const float2* wavA = g_wav + (b * FDIM + r0) * KW;
    const float2* wavB = g_wav + (b * FDIM + r1) * KW;

    u64 neg1 = dup2(-1.0f);
    u64 SA0=0, SA1=0, SB0=0, SB1=0;
    u64 CA0=0, CA1=0, CB0=0, CB1=0;

    int lx = tid >> 2;                     // x-stage lane within channel (0..63)

    for (int tb = u_lo; tb < u_hi; tb += TT) {
        int Tlen = min(TT, u_hi - tb);     // multiple of 128
        int T4 = Tlen >> 2;                // per-quarter taps, multiple of 32

        __syncthreads();                   // prev tile fully consumed

        // stage wavelet tile: wb[k] = padded-blend slot (tb+k), k in [0, Tlen+4)
        for (int k = tid; k < Tlen + 4; k += 256) {
            int u  = tb + k;
            int kg = HALFK - hw + u - 2;
            float2 v = make_float2(0.0f, 0.0f);
            if (u >= 2 && u <= n && kg <= KW - 1) {
                float2 a2 = wavA[kg], b2 = wavB[kg];
                v = make_float2(fmaf(wy1, b2.x, wy0 * a2.x),
                                fmaf(wy1, b2.y, wy0 * a2.y));
            }
            wb2[k] = v;
        }
        // stage x tile: xs[c][i] = x[base + tb + i], i in [0, span+Tlen+2)
        {
            int lenx = span + Tlen + 2;
            float* xr = xs + c * XSTRIDE;
            for (int i = lx; i < lenx; i += 64) {
                int g = base + tb + i;
                xr[i] = (g >= 0 && g < MAXT) ? xgb[g] : 0.0f;
            }
        }
        __syncthreads();

        // accumulate this quarter: local tap l = q*T4 + k, k in [0, T4)
        int lq = q * T4;                   // even (T4 mult of 32)
        const u64*  wq  = wbu + lq;
        const float* xAq = xA + lq;
        const float* xBq = xB + lq;
        u64 wp = wq[1];                    // slot u = tb+lq+1

        for (int kb = 0; kb < T4; kb += 32) {
            u64 aA0=0, aA1=0, aB0=0, aB1=0;
            #pragma unroll 4
            for (int k2 = 0; k2 < 32; k2 += 2) {
                int k = kb + k2;
                ulonglong2 W = *(const ulonglong2*)(wq + k + 2);  // 16B aligned
                u64 xa0 = dup2(xAq[k]);
                u64 xb0 = dup2(xBq[k]);
                aA0 = fma2(W.x, xa0, aA0);
                aA1 = fma2(wp,  xa0, aA1);
                aB0 = fma2(W.x, xb0, aB0);
                aB1 = fma2(wp,  xb0, aB1);
                u64 xa1 = dup2(xAq[k + 1]);
                u64 xb1 = dup2(xBq[k + 1]);
                aA0 = fma2(W.y, xa1, aA0);
                aA1 = fma2(W.x, xa1, aA1);
                aB0 = fma2(W.y, xb1, aB0);
                aB1 = fma2(W.x, xb1, aB1);
                wp = W.y;
            }
            twosum(SA0, CA0, aA0, neg1);
            twosum(SA1, CA1, aA1, neg1);
            twosum(SB0, CB0, aB0, neg1);
            twosum(SB1, CB1, aB1, neg1);
        }
    }

    u64 P[4];
    P[0] = add2(SA0, CA0); P[1] = add2(SA1, CA1);
    P[2] = add2(SB0, CB0); P[3] = add2(SB1, CB1);

    // cross-quarter reduction through smem (xs region reusable now)
    __syncthreads();
    u64* red = (u64*)xs;
    int pidx = tid & 63;
    if (q) {
        u64* dst = red + ((q - 1) * 64 + pidx) * 4;
        dst[0] = P[0]; dst[1] = P[1]; dst[2] = P[2]; dst[3] = P[3];
    }
    __syncthreads();
    if (q) return;

    #pragma unroll
    for (int qq = 0; qq < 3; ++qq) {
        u64* src = red + (qq * 64 + pidx) * 4;
        P[0] = add2(P[0], src[0]); P[1] = add2(P[1], src[1]);
        P[2] = add2(P[2], src[2]); P[3] = add2(P[3], src[3]);
    }

    float2 ZA0 = unpack2(P[0]), ZA1 = unpack2(P[1]);
    float2 ZB0 = unpack2(P[2]), ZB1 = unpack2(P[3]);

    // horizontal combine (vertical blend already folded into the wavelet)
    float rA = __fadd_rn(__fmul_rn(ZA0.x, wx0A), __fmul_rn(ZA1.x, wx1A));
    float iA = __fadd_rn(__fmul_rn(ZA0.y, wx0A), __fmul_rn(ZA1.y, wx1A));
    float rB = __fadd_rn(__fmul_rn(ZB0.x, wx0B), __fmul_rn(ZB1.x, wx1B));
    float iB = __fadd_rn(__fmul_rn(ZB0.y, wx0B), __fmul_rn(ZB1.y, wx1B));

    float magA = __fsqrt_rn(__fadd_rn(__fadd_rn(__fmul_rn(rA, rA),
                                                __fmul_rn(iA, iA)), 1e-8f));
    float magB = __fsqrt_rn(__fadd_rn(__fadd_rn(__fmul_rn(rB, rB),
                                                __fmul_rn(iB, iB)), 1e-8f));
    float phA = __fdiv_rn(atan2f(iA, rA), 3.14159274f);
    float phB = __fdiv_rn(atan2f(iB, rB), 3.14159274f);

    int cglob = cg * CPC + c;
    size_t obase = ((size_t)(b * CHAN + cglob) * 2) * FDIM + f;
    out[(obase) * TOKENS + jA]        = magA;
    out[(obase + FDIM) * TOKENS + jA] = phA;
    out[(obase) * TOKENS + jB]        = magB;
    out[(obase + FDIM) * TOKENS + jB] = phB;
}

// ---------------------------------------------------------------------------
extern "C" void kernel_launch(void* const* d_in, const int* in_sizes, int n_in,
                              void* d_out, int out_size)
{
    const float* x    = (const float*)d_in[0];
    const float* fs   = (const float*)d_in[1];
    const int*   sl   = (const int*)d_in[2];
    const float* fr   = (const float*)d_in[3];
    const float* nc   = (const float*)d_in[4];
    float* out = (float*)d_out;

    cudaFuncSetAttribute(cwt_kernel, cudaFuncAttributeMaxDynamicSharedMemorySize,
                         SMEM_BYTES);

    wavelet_kernel<<<NBF, 1024>>>(fs, fr, nc);
    dim3 grid(NBF, NCHUNK, CGRP);
    cwt_kernel<<<grid, 256, SMEM_BYTES>>>(x, fs, sl, fr, nc, out);
}